// round 13
// baseline (speedup 1.0000x reference)
#include <cuda_runtime.h>
#include <cstdint>

#define S_    512
#define P_    196
#define Q_    48
#define CB_   8
#define R_    32
#define C_    10
#define NMID  6

#define THREADS 512

// shared memory layout (floats)
#define OFF_X   0                      // 9408   x[p][q]
#define OFF_M   9408                   // 12544  M[p][ab]
#define OFF_G   21952                  // 2x8192 G tiles: half A @21952, half B @30144
#define OFF_CK  38336                  // 3072   Ck as [q][a*8+b]
#define OFF_ST  41408                  // 2*2560 state[a*320 + l*10 + c]
#define OFF_OUT 46528                  // 16
#define SMEM_FLOATS 46544

// M row stride in ulonglong2 units: 64 floats = 16 ulonglong2
#define MSTRIDE 16

__device__ __forceinline__ void ffma2(uint64_t& d, uint64_t a, uint64_t b) {
    asm("fma.rn.f32x2 %0, %1, %2, %0;" : "+l"(d) : "l"(a), "l"(b));
}
__device__ __forceinline__ uint64_t add2(uint64_t a, uint64_t b) {
    uint64_t d;
    asm("add.rn.f32x2 %0, %1, %2;" : "=l"(d) : "l"(a), "l"(b));
    return d;
}
__device__ __forceinline__ uint64_t bcast2(float v) {
    uint64_t r; unsigned u = __float_as_uint(v);
    asm("mov.b64 %0, {%1, %1};" : "=l"(r) : "r"(u));
    return r;
}
__device__ __forceinline__ float2 unpack2(uint64_t v) {
    float2 f;
    asm("mov.b64 {%0, %1}, %2;" : "=f"(f.x), "=f"(f.y) : "l"(v));
    return f;
}

// 16 packed-FMA2 block: acc[k*4+j] (+)= (m pair k) * bcast(av lane j)
#define FFMA2_BLOCK(ACC, MA, MB, AV)                                   \
    {                                                                  \
        uint64_t b0 = bcast2(AV.x), b1 = bcast2(AV.y);                 \
        uint64_t b2 = bcast2(AV.z), b3 = bcast2(AV.w);                 \
        ffma2(ACC[0],  MA.x, b0); ffma2(ACC[1],  MA.x, b1);            \
        ffma2(ACC[2],  MA.x, b2); ffma2(ACC[3],  MA.x, b3);            \
        ffma2(ACC[4],  MA.y, b0); ffma2(ACC[5],  MA.y, b1);            \
        ffma2(ACC[6],  MA.y, b2); ffma2(ACC[7],  MA.y, b3);            \
        ffma2(ACC[8],  MB.x, b0); ffma2(ACC[9],  MB.x, b1);            \
        ffma2(ACC[10], MB.x, b2); ffma2(ACC[11], MB.x, b3);            \
        ffma2(ACC[12], MB.y, b0); ffma2(ACC[13], MB.y, b1);            \
        ffma2(ACC[14], MB.y, b2); ffma2(ACC[15], MB.y, b3);            \
    }

__global__ void __launch_bounds__(THREADS, 1)
tctl_kernel(const float* __restrict__ x,
            const float* __restrict__ cf,   // [Q][CB]
            const float* __restrict__ cm,   // [NMID][CB][Q][CB]
            const float* __restrict__ cl,   // [CB][Q]
            const float* __restrict__ tf,   // [C][P][R]
            const float* __restrict__ tm,   // [NMID][R][P][R]
            const float* __restrict__ tl,   // [R][P]
            float* __restrict__ out)        // [S][C]
{
    extern __shared__ float smem[];
    float* sx     = smem + OFF_X;
    float* sM     = smem + OFF_M;
    float* sGall  = smem + OFF_G;
    float* sCk    = smem + OFF_CK;
    float* sState = smem + OFF_ST;
    float* sOut   = smem + OFF_OUT;

    const int tid = threadIdx.x;
    const int s   = blockIdx.x;

    // ---------- load x sample ----------
    {
        const float4* xg = (const float4*)(x + (size_t)s * (P_ * Q_));
        float4* sx4 = (float4*)sx;
        for (int i = tid; i < (P_ * Q_) / 4; i += THREADS) sx4[i] = xg[i];
    }
    for (int i = tid; i < Q_ * CB_; i += THREADS) sCk[i] = cf[i];
    __syncthreads();

    // ---------- carriage 1: y1[p,b] = sum_q x[p,q] cf[q,b] (into sM[p*8+b]) ----------
    for (int e = tid; e < P_ * CB_; e += THREADS) {
        int p = e >> 3, b = e & 7;
        const float* xp = sx + p * Q_;
        float acc = 0.f;
        #pragma unroll
        for (int q = 0; q < Q_; q++) acc += xp[q] * sCk[q * 8 + b];
        sM[e] = acc;
    }
    __syncthreads();

    // state0[b,r,c] = sum_p y1[p,b] * tf[c,p,r]
    if (tid < 256) {
        const int b = tid >> 5, r = tid & 31;
        float acc[C_];
        #pragma unroll
        for (int c = 0; c < C_; c++) acc[c] = 0.f;
        for (int p = 0; p < P_; p++) {
            float y = sM[p * 8 + b];
            #pragma unroll
            for (int c = 0; c < C_; c++)
                acc[c] += y * tf[((size_t)c * P_ + p) * R_ + r];
        }
        #pragma unroll
        for (int c = 0; c < C_; c++) sState[b * 320 + r * 10 + c] = acc[c];
    }

    // ---------- mid carriages: two independent 256-thread halves ----------
    const int h    = tid >> 8;          // 0 or 1 -> l range [h*16, h*16+16)
    const int t    = tid & 255;
    float*    gbuf = sGall + h * 8192;  // this half's 64x128 G tile
    // p-loop mapping within half: 8 rowGrps (8 rows) x 32 colGrps (4 cols of 128)
    const int rowGrp = t >> 5;          // 0..7
    const int colGrp = t & 31;          // 0..31
    // update mapping within half: b(8) x r(32); all 10 c as 5 packed pairs
    const int bU = t >> 5;
    const int rU = t & 31;
    const int barId = h + 1;

    for (int k = 0; k < NMID; k++) {
        const float* Ck = cm + (size_t)k * (CB_ * Q_ * CB_);
        const float* Ak = tm + (size_t)k * (R_ * P_ * R_);
        float* stCur = sState + (k & 1) * 2560;
        float* stNxt = sState + ((k & 1) ^ 1) * 2560;

        __syncthreads();  // stNxt published / scratch+G reads done / sM free

        // Ck -> sCk as [q][a*8+b]
        for (int i = tid; i < CB_ * Q_ * CB_; i += THREADS) {
            int a  = i / (Q_ * CB_);
            int qb = i % (Q_ * CB_);
            int q = qb >> 3, b = qb & 7;
            sCk[q * 64 + a * 8 + b] = Ck[i];
        }
        __syncthreads();

        // M[p][ab] = sum_q x[p,q] * Ck[a,q,b]   (packed FFMA2, all 512 threads)
        for (int e4 = tid; e4 < (P_ * 64) / 4; e4 += THREADS) {
            int p  = e4 >> 4;
            int c4 = e4 & 15;
            const float* xp = sx + p * Q_;
            const ulonglong2* ck2 = ((const ulonglong2*)sCk) + c4;
            uint64_t a01 = 0ull, a23 = 0ull;
            #pragma unroll
            for (int q = 0; q < Q_; q++) {
                uint64_t fb = bcast2(xp[q]);
                ulonglong2 ck = ck2[q * 16];
                ffma2(a01, ck.x, fb);
                ffma2(a23, ck.y, fb);
            }
            ((ulonglong2*)sM)[e4] = make_ulonglong2(a01, a23);
        }
        __syncthreads();  // sM ready; halves now run decoupled

        uint64_t ns2[5];
        #pragma unroll
        for (int j = 0; j < 5; j++) ns2[j] = 0ull;

        // 4 tiles per half over groups of 4 l-values; tile [64 rows][4*32 cols]
        for (int lt = 0; lt < 4; lt++) {
            const int   tileL = h * 16 + lt * 4;
            const int   l   = tileL + (colGrp >> 3);
            const int   r0  = (colGrp & 7) * 4;
            const float* AkL = Ak + (size_t)l * (P_ * R_) + r0;
            const ulonglong2* mbase = ((const ulonglong2*)sM) + rowGrp * 2;

            uint64_t acc[16];
            #pragma unroll
            for (int i = 0; i < 16; i++) acc[i] = 0ull;

            // unroll-4 p loop, av (LDG.128) prefetched one full body ahead (R7)
            float4 av0 = *(const float4*)(AkL + 0 * R_);
            float4 av1 = *(const float4*)(AkL + 1 * R_);
            float4 av2 = *(const float4*)(AkL + 2 * R_);
            float4 av3 = *(const float4*)(AkL + 3 * R_);
            ulonglong2 ma = mbase[0];
            ulonglong2 mb = mbase[1];

            #pragma unroll 1
            for (int pb = 0; pb < P_ - 4; pb += 4) {
                float4 avn0 = *(const float4*)(AkL + (pb + 4) * R_);
                ulonglong2 ma1 = mbase[(pb + 1) * MSTRIDE];
                ulonglong2 mb1 = mbase[(pb + 1) * MSTRIDE + 1];
                FFMA2_BLOCK(acc, ma, mb, av0)

                float4 avn1 = *(const float4*)(AkL + (pb + 5) * R_);
                ulonglong2 ma2 = mbase[(pb + 2) * MSTRIDE];
                ulonglong2 mb2 = mbase[(pb + 2) * MSTRIDE + 1];
                FFMA2_BLOCK(acc, ma1, mb1, av1)

                float4 avn2 = *(const float4*)(AkL + (pb + 6) * R_);
                ma1 = mbase[(pb + 3) * MSTRIDE];
                mb1 = mbase[(pb + 3) * MSTRIDE + 1];
                FFMA2_BLOCK(acc, ma2, mb2, av2)

                float4 avn3 = *(const float4*)(AkL + (pb + 7) * R_);
                ma = mbase[(pb + 4) * MSTRIDE];
                mb = mbase[(pb + 4) * MSTRIDE + 1];
                FFMA2_BLOCK(acc, ma1, mb1, av3)

                av0 = avn0; av1 = avn1; av2 = avn2; av3 = avn3;
            }
            // tail: p = 192..195 (av0..av3 loaded; ma/mb = row 192)
            {
                ulonglong2 n0 = mbase[193 * MSTRIDE];
                ulonglong2 n1 = mbase[193 * MSTRIDE + 1];
                FFMA2_BLOCK(acc, ma, mb, av0)
                ma = mbase[194 * MSTRIDE];
                mb = mbase[194 * MSTRIDE + 1];
                FFMA2_BLOCK(acc, n0, n1, av1)
                n0 = mbase[195 * MSTRIDE];
                n1 = mbase[195 * MSTRIDE + 1];
                FFMA2_BLOCK(acc, ma, mb, av2)
                FFMA2_BLOCK(acc, n0, n1, av3)
            }

            // write 8 rows x 4 cols to this half's G (row stride 128 fl = 32 f4)
            float4* g4 = (float4*)gbuf;
            #pragma unroll
            for (int kk = 0; kk < 4; kk++) {
                float2 l0 = unpack2(acc[kk * 4 + 0]);
                float2 l1 = unpack2(acc[kk * 4 + 1]);
                float2 l2 = unpack2(acc[kk * 4 + 2]);
                float2 l3 = unpack2(acc[kk * 4 + 3]);
                g4[(rowGrp * 8 + kk * 2 + 0) * 32 + colGrp] =
                    make_float4(l0.x, l1.x, l2.x, l3.x);
                g4[(rowGrp * 8 + kk * 2 + 1) * 32 + colGrp] =
                    make_float4(l0.y, l1.y, l2.y, l3.y);
            }
            asm volatile("bar.sync %0, 256;" :: "r"(barId) : "memory");  // publish

            // ns2[j] (+)= st-pair[j] * bcast(g)  over a(8) x lj(4)
            #pragma unroll
            for (int a = 0; a < CB_; a++) {
                #pragma unroll
                for (int lj = 0; lj < 4; lj++) {
                    float g = gbuf[(a * 8 + bU) * 128 + lj * 32 + rU];
                    uint64_t gb = bcast2(g);
                    const uint64_t* st2 =
                        (const uint64_t*)(stCur + a * 320 + (tileL + lj) * 10);
                    #pragma unroll
                    for (int j = 0; j < 5; j++) ffma2(ns2[j], st2[j], gb);
                }
            }
            asm volatile("bar.sync %0, 256;" :: "r"(barId) : "memory");  // reads done
        }

        // combine halves: A parks partials in its G buffer; B adds and writes stNxt
        if (h == 0) {
            uint64_t* scr = (uint64_t*)(sGall + t * 10);
            #pragma unroll
            for (int j = 0; j < 5; j++) scr[j] = ns2[j];
        }
        __syncthreads();
        if (h == 1) {
            const uint64_t* scr = (const uint64_t*)(sGall + t * 10);
            uint64_t* dst = (uint64_t*)(stNxt + bU * 320 + rU * 10);
            #pragma unroll
            for (int j = 0; j < 5; j++) dst[j] = add2(ns2[j], scr[j]);
        }
    }

    // ---------- last carriage ----------
    __syncthreads();

    // z[p,a] = sum_q x[p,q] cl[a,q]  (into sM[p*8+a])
    for (int e = tid; e < P_ * CB_; e += THREADS) {
        int p = e >> 3, a = e & 7;
        const float* xp  = sx + p * Q_;
        const float* cla = cl + a * Q_;
        float acc = 0.f;
        #pragma unroll
        for (int q = 0; q < Q_; q++) acc += xp[q] * cla[q];
        sM[e] = acc;
    }
    if (tid < C_) sOut[tid] = 0.f;
    __syncthreads();

    // GN[a,l] = sum_p z[p,a] tl[l,p];  out[c] = sum_{a,l} state[a,l,c]*GN[a,l]
    if (tid < 256) {
        const int a = tid >> 5, l = tid & 31;
        const float* tlr = tl + l * P_;
        float gn = 0.f;
        for (int p = 0; p < P_; p++) gn += sM[p * 8 + a] * tlr[p];

        const float* st = sState + /*final buffer 0 (NMID even)*/ a * 320 + l * 10;
        #pragma unroll
        for (int c = 0; c < C_; c++) atomicAdd(&sOut[c], st[c] * gn);
    }
    __syncthreads();

    if (tid < C_) out[(size_t)s * C_ + tid] = sOut[tid];
}

extern "C" void kernel_launch(void* const* d_in, const int* in_sizes, int n_in,
                              void* d_out, int out_size)
{
    const float* x  = (const float*)d_in[0];
    const float* cf = (const float*)d_in[1];
    const float* cm = (const float*)d_in[2];
    const float* cl = (const float*)d_in[3];
    const float* tf = (const float*)d_in[4];
    const float* tm = (const float*)d_in[5];
    const float* tl = (const float*)d_in[6];
    float* out = (float*)d_out;

    size_t shbytes = SMEM_FLOATS * sizeof(float);
    cudaFuncSetAttribute(tctl_kernel, cudaFuncAttributeMaxDynamicSharedMemorySize,
                         (int)shbytes);
    tctl_kernel<<<S_, THREADS, shbytes>>>(x, cf, cm, cl, tf, tm, tl, out);
}

// round 15
// speedup vs baseline: 1.0711x; 1.0711x over previous
#include <cuda_runtime.h>
#include <cuda_bf16.h>
#include <cstdint>

#define S_    512
#define P_    196
#define Q_    48
#define CB_   8
#define R_    32
#define C_    10
#define NMID  6

#define KP    208              // padded K (13 x 16)
#define SP    216              // smem row stride in bf16 (conflict-free)
#define NCOL  1024
#define MROWS (S_ * 64)

// ---------------- device scratch (static globals; no runtime alloc) ----------
__device__ __align__(128) __nv_bfloat16 g_Akh[(size_t)NMID * NCOL * KP]; // [step][n][k]
__device__ __align__(128) __nv_bfloat16 g_Akl[(size_t)NMID * NCOL * KP];
__device__ __align__(128) __nv_bfloat16 g_Mh[(size_t)MROWS * KP];       // [m][k]
__device__ __align__(128) __nv_bfloat16 g_Ml[(size_t)MROWS * KP];
__device__ __align__(128) float         g_G[(size_t)MROWS * NCOL];      // [m][n]
__device__ __align__(128) float         g_state[2][(size_t)S_ * 2560];  // ping-pong

// ---------------- helpers ----------------
__device__ __forceinline__ uint32_t smem_u32(const void* p) {
    uint32_t a;
    asm("{ .reg .u64 t; cvta.to.shared.u64 t, %1; cvt.u32.u64 %0, t; }"
        : "=r"(a) : "l"(p));
    return a;
}
__device__ __forceinline__ void ffma2(uint64_t& d, uint64_t a, uint64_t b) {
    asm("fma.rn.f32x2 %0, %1, %2, %0;" : "+l"(d) : "l"(a), "l"(b));
}
__device__ __forceinline__ uint64_t bcast2(float v) {
    uint64_t r; unsigned u = __float_as_uint(v);
    asm("mov.b64 %0, {%1, %1};" : "=l"(r) : "r"(u));
    return r;
}
__device__ __forceinline__ void ldm_x4(uint32_t* r, uint32_t addr) {
    asm volatile("ldmatrix.sync.aligned.m8n8.x4.shared.b16 {%0,%1,%2,%3}, [%4];"
        : "=r"(r[0]), "=r"(r[1]), "=r"(r[2]), "=r"(r[3]) : "r"(addr));
}
__device__ __forceinline__ void ldm_x2(uint32_t* r, uint32_t addr) {
    asm volatile("ldmatrix.sync.aligned.m8n8.x2.shared.b16 {%0,%1}, [%2];"
        : "=r"(r[0]), "=r"(r[1]) : "r"(addr));
}
__device__ __forceinline__ void mma_bf16(float* d, const uint32_t* a, const uint32_t* b) {
    asm volatile("mma.sync.aligned.m16n8k16.row.col.f32.bf16.bf16.f32 "
        "{%0,%1,%2,%3}, {%4,%5,%6,%7}, {%8,%9}, {%0,%1,%2,%3};"
        : "+f"(d[0]), "+f"(d[1]), "+f"(d[2]), "+f"(d[3])
        : "r"(a[0]), "r"(a[1]), "r"(a[2]), "r"(a[3]), "r"(b[0]), "r"(b[1]));
}

// ================= prep: split+transpose Ak into g_Akh/g_Akl =================
__global__ void __launch_bounds__(256, 1)
prep_ak_kernel(const float* __restrict__ tm)   // [NMID][R][P][R]
{
    const int blk = blockIdx.x;        // 0..191
    const int k = blk >> 5, l = blk & 31;
    const int t = threadIdx.x;
    const int p8 = t >> 5, r = t & 31;

    const float* src = tm + (((size_t)k * R_ + l) * P_) * R_;
    __nv_bfloat16* dh = g_Akh + ((size_t)k * NCOL + l * 32 + r) * KP;
    __nv_bfloat16* dl = g_Akl + ((size_t)k * NCOL + l * 32 + r) * KP;

    for (int it = 0; it < KP / 8; it++) {
        int p = it * 8 + p8;
        float v = (p < P_) ? src[(size_t)p * R_ + r] : 0.f;
        __nv_bfloat16 h = __float2bfloat16(v);
        __nv_bfloat16 lo = __float2bfloat16(v - __bfloat162float(h));
        dh[p] = h;
        dl[p] = lo;
    }
}

// ================= state0: first carriage =================
__global__ void __launch_bounds__(256, 1)
state0_kernel(const float* __restrict__ x, const float* __restrict__ cf,
              const float* __restrict__ tf)
{
    __shared__ float sx[P_ * Q_];
    __shared__ float sy[P_ * CB_];
    const int tid = threadIdx.x;
    const int s   = blockIdx.x;

    const float4* xg = (const float4*)(x + (size_t)s * (P_ * Q_));
    for (int i = tid; i < (P_ * Q_) / 4; i += 256) ((float4*)sx)[i] = xg[i];
    __syncthreads();

    for (int e = tid; e < P_ * CB_; e += 256) {
        int p = e >> 3, b = e & 7;
        const float* xp = sx + p * Q_;
        float acc = 0.f;
        #pragma unroll
        for (int q = 0; q < Q_; q++) acc += xp[q] * cf[q * 8 + b];
        sy[e] = acc;
    }
    __syncthreads();

    const int b = tid >> 5, r = tid & 31;
    float acc[C_];
    #pragma unroll
    for (int c = 0; c < C_; c++) acc[c] = 0.f;
    for (int p = 0; p < P_; p++) {
        float y = sy[p * 8 + b];
        #pragma unroll
        for (int c = 0; c < C_; c++)
            acc[c] += y * tf[((size_t)c * P_ + p) * R_ + r];
    }
    float* st = g_state[0] + (size_t)s * 2560 + b * 320 + r * 10;
    #pragma unroll
    for (int c = 0; c < C_; c++) st[c] = acc[c];
}

// ================= msplit: build M for step k, split to bf16 hi/lo ==========
// dynamic smem floats: sx[9408] | sCk[3072] | sM[12544]
#define MS_X  0
#define MS_CK 9408
#define MS_M  12480
#define MS_FLOATS (MS_M + 12544)

__global__ void __launch_bounds__(256, 1)
msplit_kernel(const float* __restrict__ x, const float* __restrict__ cm, int step)
{
    extern __shared__ float sm_[];
    float* sx  = sm_ + MS_X;
    float* sCk = sm_ + MS_CK;
    float* sM  = sm_ + MS_M;
    const int tid = threadIdx.x;
    const int s   = blockIdx.x;

    const float4* xg = (const float4*)(x + (size_t)s * (P_ * Q_));
    for (int i = tid; i < (P_ * Q_) / 4; i += 256) ((float4*)sx)[i] = xg[i];

    const float* Ck = cm + (size_t)step * (CB_ * Q_ * CB_);
    for (int i = tid; i < CB_ * Q_ * CB_; i += 256) {
        int a  = i / (Q_ * CB_);
        int qb = i % (Q_ * CB_);
        int q = qb >> 3, b = qb & 7;
        sCk[q * 64 + a * 8 + b] = Ck[i];
    }
    __syncthreads();

    // M[p][ab] packed FFMA2
    for (int e4 = tid; e4 < P_ * 16; e4 += 256) {
        int p  = e4 >> 4;
        int c4 = e4 & 15;
        const float* xp = sx + p * Q_;
        const ulonglong2* ck2 = ((const ulonglong2*)sCk) + c4;
        uint64_t a01 = 0ull, a23 = 0ull;
        #pragma unroll
        for (int q = 0; q < Q_; q++) {
            uint64_t fb = bcast2(xp[q]);
            ulonglong2 ck = ck2[q * 16];
            ffma2(a01, ck.x, fb);
            ffma2(a23, ck.y, fb);
        }
        ((ulonglong2*)sM)[e4] = make_ulonglong2(a01, a23);
    }
    __syncthreads();

    // transpose + split: row m = s*64 + ab, col = p (pad to 208)
    const int ab = tid >> 2, j = tid & 3;   // 4 chunks of 52 k-values
    __nv_bfloat16* dh = g_Mh + ((size_t)s * 64 + ab) * KP;
    __nv_bfloat16* dl = g_Ml + ((size_t)s * 64 + ab) * KP;
    for (int pc = 0; pc < 52; pc += 4) {
        __nv_bfloat16 h4[4], l4[4];
        #pragma unroll
        for (int u = 0; u < 4; u++) {
            int p = j * 52 + pc + u;
            float v = (p < P_) ? sM[p * 64 + ab] : 0.f;
            __nv_bfloat16 h = __float2bfloat16(v);
            h4[u] = h;
            l4[u] = __float2bfloat16(v - __bfloat162float(h));
        }
        *(uint2*)(dh + j * 52 + pc) = *(const uint2*)h4;
        *(uint2*)(dl + j * 52 + pc) = *(const uint2*)l4;
    }
}

// ================= gemm: G = Mh*Akh + Mh*Akl + Ml*Akh (mma.sync bf16) =======
// smem bytes: Ah@0, Al@55296, Bh@110592, Bl@165888; each 128*216*2 = 55296
#define GS_AH 0
#define GS_AL 55296
#define GS_BH 110592
#define GS_BL 165888
#define GS_TOTAL 221184

__global__ void __launch_bounds__(256, 1)
gemm_kernel(int step)
{
    extern __shared__ char smem[];
    const uint32_t sb = smem_u32(smem);
    const int tid = threadIdx.x, wid = tid >> 5, lid = tid & 31;
    const int mt = blockIdx.x >> 3, nt = blockIdx.x & 7;

    const __nv_bfloat16* Akh = g_Akh + (size_t)step * NCOL * KP;
    const __nv_bfloat16* Akl = g_Akl + (size_t)step * NCOL * KP;

    // ---- stage full K-panels (A: 128 m-rows, B: 128 n-rows) ----
    {
        const int r = tid >> 1, h2 = tid & 1;
        const uint4* gAh = (const uint4*)(g_Mh + ((size_t)mt * 128 + r) * KP);
        const uint4* gAl = (const uint4*)(g_Ml + ((size_t)mt * 128 + r) * KP);
        const uint4* gBh = (const uint4*)(Akh + ((size_t)nt * 128 + r) * KP);
        const uint4* gBl = (const uint4*)(Akl + ((size_t)nt * 128 + r) * KP);
        char* sAh = smem + GS_AH + r * (SP * 2);
        char* sAl = smem + GS_AL + r * (SP * 2);
        char* sBh = smem + GS_BH + r * (SP * 2);
        char* sBl = smem + GS_BL + r * (SP * 2);
        #pragma unroll
        for (int i = 0; i < 13; i++) {
            int c = i * 2 + h2;           // uint4 index 0..25 (26 x 16B = 416B)
            *(uint4*)(sAh + c * 16) = gAh[c];
            *(uint4*)(sAl + c * 16) = gAl[c];
            *(uint4*)(sBh + c * 16) = gBh[c];
            *(uint4*)(sBl + c * 16) = gBl[c];
        }
    }
    __syncthreads();

    // ---- warp tiling: 2(m) x 4(n) warps; warp tile 64m x 32n ----
    const int warp_m = wid >> 2, warp_n = wid & 3;
    // A ldmatrix lane address (x4): sub 0..3 -> (row+8?, col+8?)
    const int subA = lid >> 3, i8A = lid & 7;
    const uint32_t aRow = warp_m * 64 + (subA & 1) * 8 + i8A;
    const uint32_t aCol8 = (subA >> 1) * 8;
    const uint32_t aOffH = sb + GS_AH + aRow * (SP * 2) + aCol8 * 2;
    const uint32_t aOffL = sb + GS_AL + aRow * (SP * 2) + aCol8 * 2;
    // B ldmatrix lane address (x2): lanes 0..15 used
    const int lb = lid & 15;
    const int subB = lb >> 3, i8B = lb & 7;
    const uint32_t bRow = warp_n * 32 + i8B;
    const uint32_t bCol8 = subB * 8;
    const uint32_t bOffH = sb + GS_BH + bRow * (SP * 2) + bCol8 * 2;
    const uint32_t bOffL = sb + GS_BL + bRow * (SP * 2) + bCol8 * 2;

    float acc[4][4][4];
    #pragma unroll
    for (int i = 0; i < 4; i++)
        #pragma unroll
        for (int j = 0; j < 4; j++)
            #pragma unroll
            for (int u = 0; u < 4; u++) acc[i][j][u] = 0.f;

    #pragma unroll 1
    for (int kt = 0; kt < 13; kt++) {
        const uint32_t kOff = kt * 32;   // 16 bf16 = 32 bytes
        uint32_t ah[4][4], al[4][4];
        #pragma unroll
        for (int m4 = 0; m4 < 4; m4++) {
            ldm_x4(ah[m4], aOffH + m4 * (16 * SP * 2) + kOff);
            ldm_x4(al[m4], aOffL + m4 * (16 * SP * 2) + kOff);
        }
        #pragma unroll
        for (int n4 = 0; n4 < 4; n4++) {
            uint32_t bh[2], bl[2];
            ldm_x2(bh, bOffH + n4 * (8 * SP * 2) + kOff);
            ldm_x2(bl, bOffL + n4 * (8 * SP * 2) + kOff);
            #pragma unroll
            for (int m4 = 0; m4 < 4; m4++) {
                mma_bf16(acc[m4][n4], ah[m4], bh);
                mma_bf16(acc[m4][n4], ah[m4], bl);
                mma_bf16(acc[m4][n4], al[m4], bh);
            }
        }
    }

    // ---- epilogue: write G[m][n] ----
    const int rBase = mt * 128 + warp_m * 64 + (lid >> 2);
    const int cBase = nt * 128 + warp_n * 32 + 2 * (lid & 3);
    #pragma unroll
    for (int m4 = 0; m4 < 4; m4++) {
        #pragma unroll
        for (int n4 = 0; n4 < 4; n4++) {
            const size_t row = (size_t)(rBase + m4 * 16);
            const int col = cBase + n4 * 8;
            *(float2*)(g_G + row * NCOL + col) =
                make_float2(acc[m4][n4][0], acc[m4][n4][1]);
            *(float2*)(g_G + (row + 8) * NCOL + col) =
                make_float2(acc[m4][n4][2], acc[m4][n4][3]);
        }
    }
}

// ================= update: new_state from G =================
__global__ void __launch_bounds__(256, 1)
update_kernel(int step)
{
    __shared__ float st[2560];
    const int tid = threadIdx.x;
    const int s   = blockIdx.x;
    const int cur = step & 1, nxt = cur ^ 1;

    const float4* src = (const float4*)(g_state[cur] + (size_t)s * 2560);
    for (int i = tid; i < 640; i += 256) ((float4*)st)[i] = src[i];
    __syncthreads();

    const int b = tid >> 5, r = tid & 31;
    uint64_t ns[5];
    #pragma unroll
    for (int j = 0; j < 5; j++) ns[j] = 0ull;

    const float* Gs = g_G + (size_t)s * 64 * NCOL;
    #pragma unroll 1
    for (int a = 0; a < CB_; a++) {
        const float* grow = Gs + (size_t)(a * 8 + b) * NCOL + r;
        #pragma unroll 4
        for (int l = 0; l < 32; l++) {
            float g = grow[l * 32];
            uint64_t gb = bcast2(g);
            const uint64_t* st2 = (const uint64_t*)(st + a * 320 + l * 10);
            #pragma unroll
            for (int j = 0; j < 5; j++) ffma2(ns[j], st2[j], gb);
        }
    }
    uint64_t* dst = (uint64_t*)(g_state[nxt] + (size_t)s * 2560 + b * 320 + r * 10);
    #pragma unroll
    for (int j = 0; j < 5; j++) dst[j] = ns[j];
}

// ================= final: last carriage =================
__global__ void __launch_bounds__(256, 1)
final_kernel(const float* __restrict__ x, const float* __restrict__ cl,
             const float* __restrict__ tl, float* __restrict__ out)
{
    __shared__ float sx[P_ * Q_];
    __shared__ float sz[P_ * CB_];
    __shared__ float sOut[16];
    const int tid = threadIdx.x;
    const int s   = blockIdx.x;

    const float4* xg = (const float4*)(x + (size_t)s * (P_ * Q_));
    for (int i = tid; i < (P_ * Q_) / 4; i += 256) ((float4*)sx)[i] = xg[i];
    if (tid < C_) sOut[tid] = 0.f;
    __syncthreads();

    for (int e = tid; e < P_ * CB_; e += 256) {
        int p = e >> 3, a = e & 7;
        const float* xp  = sx + p * Q_;
        const float* cla = cl + a * Q_;
        float acc = 0.f;
        #pragma unroll
        for (int q = 0; q < Q_; q++) acc += xp[q] * cla[q];
        sz[e] = acc;
    }
    __syncthreads();

    {
        const int a = tid >> 5, l = tid & 31;
        const float* tlr = tl + l * P_;
        float gn = 0.f;
        for (int p = 0; p < P_; p++) gn += sz[p * 8 + a] * tlr[p];

        const float* st = g_state[0] + (size_t)s * 2560 + a * 320 + l * 10;
        #pragma unroll
        for (int c = 0; c < C_; c++) atomicAdd(&sOut[c], st[c] * gn);
    }
    __syncthreads();
    if (tid < C_) out[(size_t)s * C_ + tid] = sOut[tid];
}

// ================= launcher =================
extern "C" void kernel_launch(void* const* d_in, const int* in_sizes, int n_in,
                              void* d_out, int out_size)
{
    const float* x  = (const float*)d_in[0];
    const float* cf = (const float*)d_in[1];
    const float* cm = (const float*)d_in[2];
    const float* cl = (const float*)d_in[3];
    const float* tf = (const float*)d_in[4];
    const float* tm = (const float*)d_in[5];
    const float* tl = (const float*)d_in[6];
    float* out = (float*)d_out;

    cudaFuncSetAttribute(msplit_kernel, cudaFuncAttributeMaxDynamicSharedMemorySize,
                         MS_FLOATS * 4);
    cudaFuncSetAttribute(gemm_kernel, cudaFuncAttributeMaxDynamicSharedMemorySize,
                         GS_TOTAL);

    prep_ak_kernel<<<NMID * 32, 256>>>(tm);
    state0_kernel<<<S_, 256>>>(x, cf, tf);
    for (int k = 0; k < NMID; k++) {
        msplit_kernel<<<S_, 256, MS_FLOATS * 4>>>(x, cm, k);
        gemm_kernel<<<(MROWS / 128) * (NCOL / 128), 256, GS_TOTAL>>>(k);
        update_kernel<<<S_, 256>>>(k);
    }
    final_kernel<<<S_, 256>>>(x, cl, tl, out);
}

// round 16
// speedup vs baseline: 1.2168x; 1.1361x over previous
#include <cuda_runtime.h>
#include <cuda_bf16.h>
#include <cstdint>

#define S_    512
#define P_    196
#define Q_    48
#define CB_   8
#define R_    32
#define C_    10
#define NMID  6

#define KP    256              // padded K (16 x 16), zero-filled
#define KC    64               // K-chunk staged per round
#define NCH   (KP / KC)        // 4 chunks
#define SPC   72               // smem chunk row stride in bf16 (64 + 8 pad)
#define NCOL  1024
#define MROWS (S_ * 64)

// ---------------- device scratch (static globals; no runtime alloc) ----------
__device__ __align__(128) __nv_bfloat16 g_Akh[(size_t)NMID * NCOL * KP]; // [step][n][k]
__device__ __align__(128) __nv_bfloat16 g_Akl[(size_t)NMID * NCOL * KP];
__device__ __align__(128) __nv_bfloat16 g_Mh[(size_t)MROWS * KP];       // [m][k]
__device__ __align__(128) __nv_bfloat16 g_Ml[(size_t)MROWS * KP];
__device__ __align__(128) float         g_G[(size_t)MROWS * NCOL];      // [m][n]
__device__ __align__(128) float         g_state[2][(size_t)S_ * 2560];  // ping-pong

// ---------------- helpers ----------------
__device__ __forceinline__ uint32_t smem_u32(const void* p) {
    uint32_t a;
    asm("{ .reg .u64 t; cvta.to.shared.u64 t, %1; cvt.u32.u64 %0, t; }"
        : "=r"(a) : "l"(p));
    return a;
}
__device__ __forceinline__ void ffma2(uint64_t& d, uint64_t a, uint64_t b) {
    asm("fma.rn.f32x2 %0, %1, %2, %0;" : "+l"(d) : "l"(a), "l"(b));
}
__device__ __forceinline__ uint64_t bcast2(float v) {
    uint64_t r; unsigned u = __float_as_uint(v);
    asm("mov.b64 %0, {%1, %1};" : "=l"(r) : "r"(u));
    return r;
}
__device__ __forceinline__ void ldm_x4(uint32_t* r, uint32_t addr) {
    asm volatile("ldmatrix.sync.aligned.m8n8.x4.shared.b16 {%0,%1,%2,%3}, [%4];"
        : "=r"(r[0]), "=r"(r[1]), "=r"(r[2]), "=r"(r[3]) : "r"(addr));
}
__device__ __forceinline__ void ldm_x2(uint32_t* r, uint32_t addr) {
    asm volatile("ldmatrix.sync.aligned.m8n8.x2.shared.b16 {%0,%1}, [%2];"
        : "=r"(r[0]), "=r"(r[1]) : "r"(addr));
}
__device__ __forceinline__ void mma_bf16(float* d, const uint32_t* a, const uint32_t* b) {
    asm volatile("mma.sync.aligned.m16n8k16.row.col.f32.bf16.bf16.f32 "
        "{%0,%1,%2,%3}, {%4,%5,%6,%7}, {%8,%9}, {%0,%1,%2,%3};"
        : "+f"(d[0]), "+f"(d[1]), "+f"(d[2]), "+f"(d[3])
        : "r"(a[0]), "r"(a[1]), "r"(a[2]), "r"(a[3]), "r"(b[0]), "r"(b[1]));
}

// ================= prep: split+transpose Ak into g_Akh/g_Akl =================
__global__ void __launch_bounds__(256, 1)
prep_ak_kernel(const float* __restrict__ tm)   // [NMID][R][P][R]
{
    const int blk = blockIdx.x;        // 0..191
    const int k = blk >> 5, l = blk & 31;
    const int t = threadIdx.x;
    const int p8 = t >> 5, r = t & 31;

    const float* src = tm + (((size_t)k * R_ + l) * P_) * R_;
    __nv_bfloat16* dh = g_Akh + ((size_t)k * NCOL + l * 32 + r) * KP;
    __nv_bfloat16* dl = g_Akl + ((size_t)k * NCOL + l * 32 + r) * KP;

    for (int it = 0; it < KP / 8; it++) {
        int p = it * 8 + p8;
        float v = (p < P_) ? src[(size_t)p * R_ + r] : 0.f;
        __nv_bfloat16 h = __float2bfloat16(v);
        __nv_bfloat16 lo = __float2bfloat16(v - __bfloat162float(h));
        dh[p] = h;
        dl[p] = lo;
    }
}

// ================= state0: first carriage =================
__global__ void __launch_bounds__(256, 1)
state0_kernel(const float* __restrict__ x, const float* __restrict__ cf,
              const float* __restrict__ tf)
{
    __shared__ float sx[P_ * Q_];
    __shared__ float sy[P_ * CB_];
    const int tid = threadIdx.x;
    const int s   = blockIdx.x;

    const float4* xg = (const float4*)(x + (size_t)s * (P_ * Q_));
    for (int i = tid; i < (P_ * Q_) / 4; i += 256) ((float4*)sx)[i] = xg[i];
    __syncthreads();

    for (int e = tid; e < P_ * CB_; e += 256) {
        int p = e >> 3, b = e & 7;
        const float* xp = sx + p * Q_;
        float acc = 0.f;
        #pragma unroll
        for (int q = 0; q < Q_; q++) acc += xp[q] * cf[q * 8 + b];
        sy[e] = acc;
    }
    __syncthreads();

    const int b = tid >> 5, r = tid & 31;
    float acc[C_];
    #pragma unroll
    for (int c = 0; c < C_; c++) acc[c] = 0.f;
    for (int p = 0; p < P_; p++) {
        float y = sy[p * 8 + b];
        #pragma unroll
        for (int c = 0; c < C_; c++)
            acc[c] += y * tf[((size_t)c * P_ + p) * R_ + r];
    }
    float* st = g_state[0] + (size_t)s * 2560 + b * 320 + r * 10;
    #pragma unroll
    for (int c = 0; c < C_; c++) st[c] = acc[c];
}

// ================= msplit: build M for step k, split to bf16 hi/lo ==========
// dynamic smem floats: sx[9408] | sCk[3072] | sM[12544]
#define MS_X  0
#define MS_CK 9408
#define MS_M  12480
#define MS_FLOATS (MS_M + 12544)

__global__ void __launch_bounds__(256, 1)
msplit_kernel(const float* __restrict__ x, const float* __restrict__ cm, int step)
{
    extern __shared__ float sm_[];
    float* sx  = sm_ + MS_X;
    float* sCk = sm_ + MS_CK;
    float* sM  = sm_ + MS_M;
    const int tid = threadIdx.x;
    const int s   = blockIdx.x;

    const float4* xg = (const float4*)(x + (size_t)s * (P_ * Q_));
    for (int i = tid; i < (P_ * Q_) / 4; i += 256) ((float4*)sx)[i] = xg[i];

    const float* Ck = cm + (size_t)step * (CB_ * Q_ * CB_);
    for (int i = tid; i < CB_ * Q_ * CB_; i += 256) {
        int a  = i / (Q_ * CB_);
        int qb = i % (Q_ * CB_);
        int q = qb >> 3, b = qb & 7;
        sCk[q * 64 + a * 8 + b] = Ck[i];
    }
    __syncthreads();

    // M[p][ab] packed FFMA2
    for (int e4 = tid; e4 < P_ * 16; e4 += 256) {
        int p  = e4 >> 4;
        int c4 = e4 & 15;
        const float* xp = sx + p * Q_;
        const ulonglong2* ck2 = ((const ulonglong2*)sCk) + c4;
        uint64_t a01 = 0ull, a23 = 0ull;
        #pragma unroll
        for (int q = 0; q < Q_; q++) {
            uint64_t fb = bcast2(xp[q]);
            ulonglong2 ck = ck2[q * 16];
            ffma2(a01, ck.x, fb);
            ffma2(a23, ck.y, fb);
        }
        ((ulonglong2*)sM)[e4] = make_ulonglong2(a01, a23);
    }
    __syncthreads();

    // transpose + split: row m = s*64 + ab, col = p (zero-pad to 256)
    const int ab = tid >> 2, j = tid & 3;   // 4 chunks of 64 k-values
    __nv_bfloat16* dh = g_Mh + ((size_t)s * 64 + ab) * KP + j * 64;
    __nv_bfloat16* dl = g_Ml + ((size_t)s * 64 + ab) * KP + j * 64;
    for (int pc = 0; pc < 64; pc += 8) {
        __nv_bfloat16 h8[8], l8[8];
        #pragma unroll
        for (int u = 0; u < 8; u++) {
            int p = j * 64 + pc + u;
            float v = (p < P_) ? sM[p * 64 + ab] : 0.f;
            __nv_bfloat16 h = __float2bfloat16(v);
            h8[u] = h;
            l8[u] = __float2bfloat16(v - __bfloat162float(h));
        }
        *(uint4*)(dh + pc) = *(const uint4*)h8;
        *(uint4*)(dl + pc) = *(const uint4*)l8;
    }
}

// ================= gemm: G = Mh*Akh + Mh*Akl + Ml*Akh (mma.sync bf16) =======
// K staged in chunks of KC=64 -> smem 4 panels x 128 x 72 bf16 = 73728 B
// -> 2 CTAs/SM (occupancy fix vs full-K staging)
#define GP   (128 * SPC * 2)   // 18432 B per panel
#define GS_AH 0
#define GS_AL GP
#define GS_BH (2 * GP)
#define GS_BL (3 * GP)
#define GS_TOTAL (4 * GP)      // 73728

__global__ void __launch_bounds__(256, 2)
gemm_kernel(int step)
{
    extern __shared__ char smem[];
    const uint32_t sb = smem_u32(smem);
    const int tid = threadIdx.x, wid = tid >> 5, lid = tid & 31;
    const int mt = blockIdx.x >> 3, nt = blockIdx.x & 7;

    const __nv_bfloat16* Akh = g_Akh + (size_t)step * NCOL * KP;
    const __nv_bfloat16* Akl = g_Akl + (size_t)step * NCOL * KP;

    // warp tiling: 2(m) x 4(n) warps; warp tile 64m x 32n
    const int warp_m = wid >> 2, warp_n = wid & 3;
    const int subA = lid >> 3, i8A = lid & 7;
    const uint32_t aRow = warp_m * 64 + (subA & 1) * 8 + i8A;
    const uint32_t aCol8 = (subA >> 1) * 8;
    const uint32_t aOffH = sb + GS_AH + aRow * (SPC * 2) + aCol8 * 2;
    const uint32_t aOffL = sb + GS_AL + aRow * (SPC * 2) + aCol8 * 2;
    const int lb = lid & 15;
    const int subB = lb >> 3, i8B = lb & 7;
    const uint32_t bRow = warp_n * 32 + i8B;
    const uint32_t bCol8 = subB * 8;
    const uint32_t bOffH = sb + GS_BH + bRow * (SPC * 2) + bCol8 * 2;
    const uint32_t bOffL = sb + GS_BL + bRow * (SPC * 2) + bCol8 * 2;

    // staging mapping: row = tid>>1, half = tid&1 -> 4 consecutive uint4 (64B)
    const int sRow = tid >> 1, sHalf = tid & 1;
    const uint4* gAh4 = (const uint4*)(g_Mh + ((size_t)mt * 128 + sRow) * KP);
    const uint4* gAl4 = (const uint4*)(g_Ml + ((size_t)mt * 128 + sRow) * KP);
    const uint4* gBh4 = (const uint4*)(Akh + ((size_t)nt * 128 + sRow) * KP);
    const uint4* gBl4 = (const uint4*)(Akl + ((size_t)nt * 128 + sRow) * KP);
    char* sAh = smem + GS_AH + sRow * (SPC * 2);
    char* sAl = smem + GS_AL + sRow * (SPC * 2);
    char* sBh = smem + GS_BH + sRow * (SPC * 2);
    char* sBl = smem + GS_BL + sRow * (SPC * 2);

    float acc[4][4][4];
    #pragma unroll
    for (int i = 0; i < 4; i++)
        #pragma unroll
        for (int j = 0; j < 4; j++)
            #pragma unroll
            for (int u = 0; u < 4; u++) acc[i][j][u] = 0.f;

    #pragma unroll 1
    for (int ch = 0; ch < NCH; ch++) {
        if (ch > 0) __syncthreads();   // previous chunk fully consumed

        // stage chunk ch: 64 bf16 (128B) per row per panel
        {
            const int cbase = ch * (KC / 8);   // uint4 index of chunk start
            #pragma unroll
            for (int u = 0; u < 4; u++) {
                int c = sHalf * 4 + u;
                *(uint4*)(sAh + c * 16) = gAh4[cbase + c];
                *(uint4*)(sAl + c * 16) = gAl4[cbase + c];
                *(uint4*)(sBh + c * 16) = gBh4[cbase + c];
                *(uint4*)(sBl + c * 16) = gBl4[cbase + c];
            }
        }
        __syncthreads();

        #pragma unroll 1
        for (int ktl = 0; ktl < KC / 16; ktl++) {
            const uint32_t kOff = ktl * 32;  // 16 bf16 = 32 B
            uint32_t ah[4][4], al[4][4];
            #pragma unroll
            for (int m4 = 0; m4 < 4; m4++) {
                ldm_x4(ah[m4], aOffH + m4 * (16 * SPC * 2) + kOff);
                ldm_x4(al[m4], aOffL + m4 * (16 * SPC * 2) + kOff);
            }
            #pragma unroll
            for (int n4 = 0; n4 < 4; n4++) {
                uint32_t bh[2], bl[2];
                ldm_x2(bh, bOffH + n4 * (8 * SPC * 2) + kOff);
                ldm_x2(bl, bOffL + n4 * (8 * SPC * 2) + kOff);
                #pragma unroll
                for (int m4 = 0; m4 < 4; m4++) {
                    mma_bf16(acc[m4][n4], ah[m4], bh);
                    mma_bf16(acc[m4][n4], ah[m4], bl);
                    mma_bf16(acc[m4][n4], al[m4], bh);
                }
            }
        }
    }

    // ---- epilogue: write G[m][n] ----
    const int rBase = mt * 128 + warp_m * 64 + (lid >> 2);
    const int cBase = nt * 128 + warp_n * 32 + 2 * (lid & 3);
    #pragma unroll
    for (int m4 = 0; m4 < 4; m4++) {
        #pragma unroll
        for (int n4 = 0; n4 < 4; n4++) {
            const size_t row = (size_t)(rBase + m4 * 16);
            const int col = cBase + n4 * 8;
            *(float2*)(g_G + row * NCOL + col) =
                make_float2(acc[m4][n4][0], acc[m4][n4][1]);
            *(float2*)(g_G + (row + 8) * NCOL + col) =
                make_float2(acc[m4][n4][2], acc[m4][n4][3]);
        }
    }
}

// ================= update: new_state from G =================
__global__ void __launch_bounds__(256, 1)
update_kernel(int step)
{
    __shared__ float st[2560];
    const int tid = threadIdx.x;
    const int s   = blockIdx.x;
    const int cur = step & 1, nxt = cur ^ 1;

    const float4* src = (const float4*)(g_state[cur] + (size_t)s * 2560);
    for (int i = tid; i < 640; i += 256) ((float4*)st)[i] = src[i];
    __syncthreads();

    const int b = tid >> 5, r = tid & 31;
    uint64_t ns[5];
    #pragma unroll
    for (int j = 0; j < 5; j++) ns[j] = 0ull;

    const float* Gs = g_G + (size_t)s * 64 * NCOL;
    #pragma unroll 1
    for (int a = 0; a < CB_; a++) {
        const float* grow = Gs + (size_t)(a * 8 + b) * NCOL + r;
        #pragma unroll 4
        for (int l = 0; l < 32; l++) {
            float g = grow[l * 32];
            uint64_t gb = bcast2(g);
            const uint64_t* st2 = (const uint64_t*)(st + a * 320 + l * 10);
            #pragma unroll
            for (int j = 0; j < 5; j++) ffma2(ns[j], st2[j], gb);
        }
    }
    uint64_t* dst = (uint64_t*)(g_state[nxt] + (size_t)s * 2560 + b * 320 + r * 10);
    #pragma unroll
    for (int j = 0; j < 5; j++) dst[j] = ns[j];
}

// ================= final: last carriage =================
__global__ void __launch_bounds__(256, 1)
final_kernel(const float* __restrict__ x, const float* __restrict__ cl,
             const float* __restrict__ tl, float* __restrict__ out)
{
    __shared__ float sx[P_ * Q_];
    __shared__ float sz[P_ * CB_];
    __shared__ float sOut[16];
    const int tid = threadIdx.x;
    const int s   = blockIdx.x;

    const float4* xg = (const float4*)(x + (size_t)s * (P_ * Q_));
    for (int i = tid; i < (P_ * Q_) / 4; i += 256) ((float4*)sx)[i] = xg[i];
    if (tid < C_) sOut[tid] = 0.f;
    __syncthreads();

    for (int e = tid; e < P_ * CB_; e += 256) {
        int p = e >> 3, a = e & 7;
        const float* xp  = sx + p * Q_;
        const float* cla = cl + a * Q_;
        float acc = 0.f;
        #pragma unroll
        for (int q = 0; q < Q_; q++) acc += xp[q] * cla[q];
        sz[e] = acc;
    }
    __syncthreads();

    {
        const int a = tid >> 5, l = tid & 31;
        const float* tlr = tl + l * P_;
        float gn = 0.f;
        for (int p = 0; p < P_; p++) gn += sz[p * 8 + a] * tlr[p];

        const float* st = g_state[0] + (size_t)s * 2560 + a * 320 + l * 10;
        #pragma unroll
        for (int c = 0; c < C_; c++) atomicAdd(&sOut[c], st[c] * gn);
    }
    __syncthreads();
    if (tid < C_) out[(size_t)s * C_ + tid] = sOut[tid];
}

// ================= launcher =================
extern "C" void kernel_launch(void* const* d_in, const int* in_sizes, int n_in,
                              void* d_out, int out_size)
{
    const float* x  = (const float*)d_in[0];
    const float* cf = (const float*)d_in[1];
    const float* cm = (const float*)d_in[2];
    const float* cl = (const float*)d_in[3];
    const float* tf = (const float*)d_in[4];
    const float* tm = (const float*)d_in[5];
    const float* tl = (const float*)d_in[6];
    float* out = (float*)d_out;

    cudaFuncSetAttribute(msplit_kernel, cudaFuncAttributeMaxDynamicSharedMemorySize,
                         MS_FLOATS * 4);
    cudaFuncSetAttribute(gemm_kernel, cudaFuncAttributeMaxDynamicSharedMemorySize,
                         GS_TOTAL);

    prep_ak_kernel<<<NMID * 32, 256>>>(tm);
    state0_kernel<<<S_, 256>>>(x, cf, tf);
    for (int k = 0; k < NMID; k++) {
        msplit_kernel<<<S_, 256, MS_FLOATS * 4>>>(x, cm, k);
        gemm_kernel<<<(MROWS / 128) * (NCOL / 128), 256, GS_TOTAL>>>(k);
        update_kernel<<<S_, 256>>>(k);
    }
    final_kernel<<<S_, 256>>>(x, cl, tl, out);
}

// round 17
// speedup vs baseline: 1.3062x; 1.0735x over previous
#include <cuda_runtime.h>
#include <cuda_bf16.h>
#include <cstdint>

#define S_    512
#define P_    196
#define Q_    48
#define CB_   8
#define R_    32
#define C_    10
#define NMID  6

#define KP    256              // padded K (16 x 16), zero-filled
#define KC    64               // K-chunk staged per round
#define NCH   (KP / KC)        // 4 chunks
#define SPC   72               // smem chunk row stride in bf16 (64 + 8 pad)
#define NCOL  1024
#define MROWS (S_ * 64)

// ---------------- device scratch (static globals; no runtime alloc) ----------
__device__ __align__(128) __nv_bfloat16 g_Akh[(size_t)NMID * NCOL * KP];  // [step][n][k]
__device__ __align__(128) __nv_bfloat16 g_Akl[(size_t)NMID * NCOL * KP];
__device__ __align__(128) __nv_bfloat16 g_Mh6[(size_t)NMID * MROWS * KP]; // [step][m][k]
__device__ __align__(128) __nv_bfloat16 g_Ml6[(size_t)NMID * MROWS * KP];
__device__ __align__(128) float         g_G6[(size_t)NMID * MROWS * NCOL];// [step][m][n]
__device__ __align__(128) float         g_state0[(size_t)S_ * 2560];

// ---------------- helpers ----------------
__device__ __forceinline__ uint32_t smem_u32(const void* p) {
    uint32_t a;
    asm("{ .reg .u64 t; cvta.to.shared.u64 t, %1; cvt.u32.u64 %0, t; }"
        : "=r"(a) : "l"(p));
    return a;
}
__device__ __forceinline__ void ffma2(uint64_t& d, uint64_t a, uint64_t b) {
    asm("fma.rn.f32x2 %0, %1, %2, %0;" : "+l"(d) : "l"(a), "l"(b));
}
__device__ __forceinline__ uint64_t bcast2(float v) {
    uint64_t r; unsigned u = __float_as_uint(v);
    asm("mov.b64 %0, {%1, %1};" : "=l"(r) : "r"(u));
    return r;
}
__device__ __forceinline__ void ldm_x4(uint32_t* r, uint32_t addr) {
    asm volatile("ldmatrix.sync.aligned.m8n8.x4.shared.b16 {%0,%1,%2,%3}, [%4];"
        : "=r"(r[0]), "=r"(r[1]), "=r"(r[2]), "=r"(r[3]) : "r"(addr));
}
__device__ __forceinline__ void ldm_x2(uint32_t* r, uint32_t addr) {
    asm volatile("ldmatrix.sync.aligned.m8n8.x2.shared.b16 {%0,%1}, [%2];"
        : "=r"(r[0]), "=r"(r[1]) : "r"(addr));
}
__device__ __forceinline__ void mma_bf16(float* d, const uint32_t* a, const uint32_t* b) {
    asm volatile("mma.sync.aligned.m16n8k16.row.col.f32.bf16.bf16.f32 "
        "{%0,%1,%2,%3}, {%4,%5,%6,%7}, {%8,%9}, {%0,%1,%2,%3};"
        : "+f"(d[0]), "+f"(d[1]), "+f"(d[2]), "+f"(d[3])
        : "r"(a[0]), "r"(a[1]), "r"(a[2]), "r"(a[3]), "r"(b[0]), "r"(b[1]));
}

// ================= prep: split+transpose Ak into g_Akh/g_Akl =================
__global__ void __launch_bounds__(256, 1)
prep_ak_kernel(const float* __restrict__ tm)   // [NMID][R][P][R]
{
    const int blk = blockIdx.x;        // 0..191
    const int k = blk >> 5, l = blk & 31;
    const int t = threadIdx.x;
    const int p8 = t >> 5, r = t & 31;

    const float* src = tm + (((size_t)k * R_ + l) * P_) * R_;
    __nv_bfloat16* dh = g_Akh + ((size_t)k * NCOL + l * 32 + r) * KP;
    __nv_bfloat16* dl = g_Akl + ((size_t)k * NCOL + l * 32 + r) * KP;

    for (int it = 0; it < KP / 8; it++) {
        int p = it * 8 + p8;
        float v = (p < P_) ? src[(size_t)p * R_ + r] : 0.f;
        __nv_bfloat16 h = __float2bfloat16(v);
        __nv_bfloat16 lo = __float2bfloat16(v - __bfloat162float(h));
        dh[p] = h;
        dl[p] = lo;
    }
}

// ===== msplit_all: state0 + M build/split for ALL steps, one block/sample ====
// dynamic smem floats: sx[9408] | sCk[3072] | sM[12544]
#define MS_X  0
#define MS_CK 9408
#define MS_M  12480
#define MS_FLOATS (MS_M + 12544)

__global__ void __launch_bounds__(256, 1)
msplit_all_kernel(const float* __restrict__ x, const float* __restrict__ cf,
                  const float* __restrict__ cm, const float* __restrict__ tf)
{
    extern __shared__ float sm_[];
    float* sx  = sm_ + MS_X;
    float* sCk = sm_ + MS_CK;
    float* sM  = sm_ + MS_M;
    const int tid = threadIdx.x;
    const int s   = blockIdx.x;

    const float4* xg = (const float4*)(x + (size_t)s * (P_ * Q_));
    for (int i = tid; i < (P_ * Q_) / 4; i += 256) ((float4*)sx)[i] = xg[i];
    __syncthreads();

    // ---- state0 (fused first carriage) ----
    for (int e = tid; e < P_ * CB_; e += 256) {
        int p = e >> 3, b = e & 7;
        const float* xp = sx + p * Q_;
        float acc = 0.f;
        #pragma unroll
        for (int q = 0; q < Q_; q++) acc += xp[q] * cf[q * 8 + b];
        sM[e] = acc;
    }
    __syncthreads();
    {
        const int b = tid >> 5, r = tid & 31;
        float acc[C_];
        #pragma unroll
        for (int c = 0; c < C_; c++) acc[c] = 0.f;
        for (int p = 0; p < P_; p++) {
            float y = sM[p * 8 + b];
            #pragma unroll
            for (int c = 0; c < C_; c++)
                acc[c] += y * tf[((size_t)c * P_ + p) * R_ + r];
        }
        float* st = g_state0 + (size_t)s * 2560 + b * 320 + r * 10;
        #pragma unroll
        for (int c = 0; c < C_; c++) st[c] = acc[c];
    }

    // ---- M for each step ----
    for (int k = 0; k < NMID; k++) {
        __syncthreads();    // prev split reads of sM / state0 reads done

        const float* Ck = cm + (size_t)k * (CB_ * Q_ * CB_);
        for (int i = tid; i < CB_ * Q_ * CB_; i += 256) {
            int a  = i / (Q_ * CB_);
            int qb = i % (Q_ * CB_);
            int q = qb >> 3, b = qb & 7;
            sCk[q * 64 + a * 8 + b] = Ck[i];
        }
        __syncthreads();

        for (int e4 = tid; e4 < P_ * 16; e4 += 256) {
            int p  = e4 >> 4;
            int c4 = e4 & 15;
            const float* xp = sx + p * Q_;
            const ulonglong2* ck2 = ((const ulonglong2*)sCk) + c4;
            uint64_t a01 = 0ull, a23 = 0ull;
            #pragma unroll
            for (int q = 0; q < Q_; q++) {
                uint64_t fb = bcast2(xp[q]);
                ulonglong2 ck = ck2[q * 16];
                ffma2(a01, ck.x, fb);
                ffma2(a23, ck.y, fb);
            }
            ((ulonglong2*)sM)[e4] = make_ulonglong2(a01, a23);
        }
        __syncthreads();

        // transpose + split: row m = s*64 + ab, col = p (zero-pad to 256)
        const int ab = tid >> 2, j = tid & 3;   // 4 chunks of 64 k-values
        __nv_bfloat16* dh = g_Mh6 + (size_t)k * MROWS * KP + ((size_t)s * 64 + ab) * KP + j * 64;
        __nv_bfloat16* dl = g_Ml6 + (size_t)k * MROWS * KP + ((size_t)s * 64 + ab) * KP + j * 64;
        for (int pc = 0; pc < 64; pc += 8) {
            __nv_bfloat16 h8[8], l8[8];
            #pragma unroll
            for (int u = 0; u < 8; u++) {
                int p = j * 64 + pc + u;
                float v = (p < P_) ? sM[p * 64 + ab] : 0.f;
                __nv_bfloat16 h = __float2bfloat16(v);
                h8[u] = h;
                l8[u] = __float2bfloat16(v - __bfloat162float(h));
            }
            *(uint4*)(dh + pc) = *(const uint4*)h8;
            *(uint4*)(dl + pc) = *(const uint4*)l8;
        }
    }
}

// ===== gemm_all: G_k = Mh*Akh + Mh*Akl + Ml*Akh for ALL k (mma.sync bf16) ====
// K staged in chunks of KC=64 -> smem 4 panels x 128 x 72 bf16 = 73728 B, 2 CTA/SM
#define GP   (128 * SPC * 2)   // 18432 B per panel
#define GS_AH 0
#define GS_AL GP
#define GS_BH (2 * GP)
#define GS_BL (3 * GP)
#define GS_TOTAL (4 * GP)      // 73728

__global__ void __launch_bounds__(256, 2)
gemm_all_kernel()
{
    extern __shared__ char smem[];
    const uint32_t sb = smem_u32(smem);
    const int tid = threadIdx.x, wid = tid >> 5, lid = tid & 31;
    const int mt = blockIdx.x >> 3, nt = blockIdx.x & 7;
    const int step = blockIdx.y;

    const __nv_bfloat16* Akh = g_Akh + (size_t)step * NCOL * KP;
    const __nv_bfloat16* Akl = g_Akl + (size_t)step * NCOL * KP;
    const __nv_bfloat16* Mh  = g_Mh6 + (size_t)step * MROWS * KP;
    const __nv_bfloat16* Ml  = g_Ml6 + (size_t)step * MROWS * KP;
    float*               Gd  = g_G6  + (size_t)step * MROWS * NCOL;

    // warp tiling: 2(m) x 4(n) warps; warp tile 64m x 32n
    const int warp_m = wid >> 2, warp_n = wid & 3;
    const int subA = lid >> 3, i8A = lid & 7;
    const uint32_t aRow = warp_m * 64 + (subA & 1) * 8 + i8A;
    const uint32_t aCol8 = (subA >> 1) * 8;
    const uint32_t aOffH = sb + GS_AH + aRow * (SPC * 2) + aCol8 * 2;
    const uint32_t aOffL = sb + GS_AL + aRow * (SPC * 2) + aCol8 * 2;
    const int lb = lid & 15;
    const int subB = lb >> 3, i8B = lb & 7;
    const uint32_t bRow = warp_n * 32 + i8B;
    const uint32_t bCol8 = subB * 8;
    const uint32_t bOffH = sb + GS_BH + bRow * (SPC * 2) + bCol8 * 2;
    const uint32_t bOffL = sb + GS_BL + bRow * (SPC * 2) + bCol8 * 2;

    // staging mapping: row = tid>>1, half = tid&1 -> 4 consecutive uint4 (64B)
    const int sRow = tid >> 1, sHalf = tid & 1;
    const uint4* gAh4 = (const uint4*)(Mh + ((size_t)mt * 128 + sRow) * KP);
    const uint4* gAl4 = (const uint4*)(Ml + ((size_t)mt * 128 + sRow) * KP);
    const uint4* gBh4 = (const uint4*)(Akh + ((size_t)nt * 128 + sRow) * KP);
    const uint4* gBl4 = (const uint4*)(Akl + ((size_t)nt * 128 + sRow) * KP);
    char* sAh = smem + GS_AH + sRow * (SPC * 2);
    char* sAl = smem + GS_AL + sRow * (SPC * 2);
    char* sBh = smem + GS_BH + sRow * (SPC * 2);
    char* sBl = smem + GS_BL + sRow * (SPC * 2);

    float acc[4][4][4];
    #pragma unroll
    for (int i = 0; i < 4; i++)
        #pragma unroll
        for (int j = 0; j < 4; j++)
            #pragma unroll
            for (int u = 0; u < 4; u++) acc[i][j][u] = 0.f;

    #pragma unroll 1
    for (int ch = 0; ch < NCH; ch++) {
        if (ch > 0) __syncthreads();   // previous chunk fully consumed

        {
            const int cbase = ch * (KC / 8);
            #pragma unroll
            for (int u = 0; u < 4; u++) {
                int c = sHalf * 4 + u;
                *(uint4*)(sAh + c * 16) = gAh4[cbase + c];
                *(uint4*)(sAl + c * 16) = gAl4[cbase + c];
                *(uint4*)(sBh + c * 16) = gBh4[cbase + c];
                *(uint4*)(sBl + c * 16) = gBl4[cbase + c];
            }
        }
        __syncthreads();

        #pragma unroll 1
        for (int ktl = 0; ktl < KC / 16; ktl++) {
            const uint32_t kOff = ktl * 32;
            uint32_t ah[4][4], al[4][4];
            #pragma unroll
            for (int m4 = 0; m4 < 4; m4++) {
                ldm_x4(ah[m4], aOffH + m4 * (16 * SPC * 2) + kOff);
                ldm_x4(al[m4], aOffL + m4 * (16 * SPC * 2) + kOff);
            }
            #pragma unroll
            for (int n4 = 0; n4 < 4; n4++) {
                uint32_t bh[2], bl[2];
                ldm_x2(bh, bOffH + n4 * (8 * SPC * 2) + kOff);
                ldm_x2(bl, bOffL + n4 * (8 * SPC * 2) + kOff);
                #pragma unroll
                for (int m4 = 0; m4 < 4; m4++) {
                    mma_bf16(acc[m4][n4], ah[m4], bh);
                    mma_bf16(acc[m4][n4], ah[m4], bl);
                    mma_bf16(acc[m4][n4], al[m4], bh);
                }
            }
        }
    }

    // ---- epilogue ----
    const int rBase = mt * 128 + warp_m * 64 + (lid >> 2);
    const int cBase = nt * 128 + warp_n * 32 + 2 * (lid & 3);
    #pragma unroll
    for (int m4 = 0; m4 < 4; m4++) {
        #pragma unroll
        for (int n4 = 0; n4 < 4; n4++) {
            const size_t row = (size_t)(rBase + m4 * 16);
            const int col = cBase + n4 * 8;
            *(float2*)(Gd + row * NCOL + col) =
                make_float2(acc[m4][n4][0], acc[m4][n4][1]);
            *(float2*)(Gd + (row + 8) * NCOL + col) =
                make_float2(acc[m4][n4][2], acc[m4][n4][3]);
        }
    }
}

// ===== update_final: all 6 state updates (smem ping-pong) + last carriage ====
// dynamic smem floats: st[0..5120) | sx[5120..14528) | sz[14528..16096) | sOut[16096..16112)
#define UF_ST  0
#define UF_X   5120
#define UF_Z   14528
#define UF_OUT 16096
#define UF_FLOATS 16112

__global__ void __launch_bounds__(256, 1)
update_final_kernel(const float* __restrict__ x, const float* __restrict__ cl,
                    const float* __restrict__ tl, float* __restrict__ out)
{
    extern __shared__ float sm_[];
    float* st  = sm_ + UF_ST;     // 2 x 2560 ping-pong
    float* sx  = sm_ + UF_X;
    float* sz  = sm_ + UF_Z;
    float* sOut = sm_ + UF_OUT;
    const int tid = threadIdx.x;
    const int s   = blockIdx.x;
    const int b = tid >> 5, r = tid & 31;

    {
        const float4* src = (const float4*)(g_state0 + (size_t)s * 2560);
        for (int i = tid; i < 640; i += 256) ((float4*)st)[i] = src[i];
    }
    __syncthreads();

    #pragma unroll 1
    for (int k = 0; k < NMID; k++) {
        const float* cur = st + (k & 1) * 2560;
        float* nxt = st + ((k & 1) ^ 1) * 2560;

        uint64_t ns[5];
        #pragma unroll
        for (int j = 0; j < 5; j++) ns[j] = 0ull;

        const float* Gs = g_G6 + (size_t)k * MROWS * NCOL + (size_t)s * 64 * NCOL;
        #pragma unroll 1
        for (int a = 0; a < CB_; a++) {
            const float* grow = Gs + (size_t)(a * 8 + b) * NCOL + r;
            #pragma unroll 4
            for (int l = 0; l < 32; l++) {
                float g = grow[l * 32];
                uint64_t gb = bcast2(g);
                const uint64_t* st2 = (const uint64_t*)(cur + a * 320 + l * 10);
                #pragma unroll
                for (int j = 0; j < 5; j++) ffma2(ns[j], st2[j], gb);
            }
        }
        uint64_t* dst = (uint64_t*)(nxt + b * 320 + r * 10);
        #pragma unroll
        for (int j = 0; j < 5; j++) dst[j] = ns[j];
        __syncthreads();   // nxt published before next iteration reads it
    }
    // final state is in st buffer 0 (6 updates: last write to buf 0)

    // ---- last carriage ----
    {
        const float4* xg = (const float4*)(x + (size_t)s * (P_ * Q_));
        for (int i = tid; i < (P_ * Q_) / 4; i += 256) ((float4*)sx)[i] = xg[i];
    }
    if (tid < C_) sOut[tid] = 0.f;
    __syncthreads();

    for (int e = tid; e < P_ * CB_; e += 256) {
        int p = e >> 3, a = e & 7;
        const float* xp  = sx + p * Q_;
        const float* cla = cl + a * Q_;
        float acc = 0.f;
        #pragma unroll
        for (int q = 0; q < Q_; q++) acc += xp[q] * cla[q];
        sz[e] = acc;
    }
    __syncthreads();

    {
        const int a = tid >> 5, l = tid & 31;
        const float* tlr = tl + l * P_;
        float gn = 0.f;
        for (int p = 0; p < P_; p++) gn += sz[p * 8 + a] * tlr[p];

        const float* stf = st + a * 320 + l * 10;   // buffer 0
        #pragma unroll
        for (int c = 0; c < C_; c++) atomicAdd(&sOut[c], stf[c] * gn);
    }
    __syncthreads();
    if (tid < C_) out[(size_t)s * C_ + tid] = sOut[tid];
}

// ================= launcher =================
extern "C" void kernel_launch(void* const* d_in, const int* in_sizes, int n_in,
                              void* d_out, int out_size)
{
    const float* x  = (const float*)d_in[0];
    const float* cf = (const float*)d_in[1];
    const float* cm = (const float*)d_in[2];
    const float* cl = (const float*)d_in[3];
    const float* tf = (const float*)d_in[4];
    const float* tm = (const float*)d_in[5];
    const float* tl = (const float*)d_in[6];
    float* out = (float*)d_out;

    cudaFuncSetAttribute(msplit_all_kernel, cudaFuncAttributeMaxDynamicSharedMemorySize,
                         MS_FLOATS * 4);
    cudaFuncSetAttribute(gemm_all_kernel, cudaFuncAttributeMaxDynamicSharedMemorySize,
                         GS_TOTAL);
    cudaFuncSetAttribute(update_final_kernel, cudaFuncAttributeMaxDynamicSharedMemorySize,
                         UF_FLOATS * 4);

    prep_ak_kernel<<<NMID * 32, 256>>>(tm);
    msplit_all_kernel<<<S_, 256, MS_FLOATS * 4>>>(x, cf, cm, tf);
    gemm_all_kernel<<<dim3(2048, NMID), 256, GS_TOTAL>>>();
    update_final_kernel<<<S_, 256, UF_FLOATS * 4>>>(x, cl, tl, out);
}